// round 10
// baseline (speedup 1.0000x reference)
#include <cuda_runtime.h>

#define NB    4096
#define ND    1024
#define NC    10
#define TILE  64
#define KC    16          // k elements per smem chunk
#define NCHUNK (ND / KC)  // 64
#define MAXT  2080        // worst-case active tiles (one class: 64*65/2)
#define HBYTES 32768      // per-half smem: A(2x8KB) + B(2x8KB)
#define SMEMSZ (2 * HBYTES + 512)

// ---------------- device scratch (no allocations allowed) ----------------
__device__ __align__(16) float2 g_pk[NB * ND];   // interleaved (ghat, xhat) rows, 32 MB
__device__ int    g_cls[NB];
__device__ int    g_counts[NC];
__device__ int    g_offsets[NC];
__device__ int    g_order[NB];     // row indices stably sorted by class
__device__ int    g_tiles[MAXT];   // packed active tiles: c | ti<<4 | tj<<10
__device__ int    g_ntiles;
__device__ float  g_partials[MAXT];

// packed f32x2 FMA: d.lo += a.lo*b.lo ; d.hi += a.hi*b.hi   (SASS FFMA2)
__device__ __forceinline__ void ffma2(unsigned long long& d,
                                      unsigned long long a,
                                      unsigned long long b) {
    asm("fma.rn.f32x2 %0, %1, %2, %0;" : "+l"(d) : "l"(a), "l"(b));
}

__device__ __forceinline__ unsigned su32(const void* p) {
    return (unsigned)__cvta_generic_to_shared(p);
}
#define CP_ASYNC16(dst, src) \
    asm volatile("cp.async.cg.shared.global [%0], [%1], 16;" :: "r"(dst), "l"(src))
#define CP_COMMIT()  asm volatile("cp.async.commit_group;" ::: "memory")
#define CP_WAIT(n)   asm volatile("cp.async.wait_group %0;" :: "n"(n) : "memory")

// ---------------- kernel 0: zero class counters ----------------
__global__ void k_zero() {
    if (threadIdx.x < NC) g_counts[threadIdx.x] = 0;
}

// ---------------- kernel 1: per-row preprocess ----------------
__global__ void __launch_bounds__(256) k_prep(const float* __restrict__ outputs,
                                              const float* __restrict__ grad,
                                              const float* __restrict__ xin) {
    const int row = blockIdx.x;
    const int tid = threadIdx.x;

    const float4 gv = reinterpret_cast<const float4*>(grad + row * ND)[tid];
    const float4 xv = reinterpret_cast<const float4*>(xin  + row * ND)[tid];

    float mn = fminf(fminf(gv.x, gv.y), fminf(gv.z, gv.w));
    float mx = fmaxf(fmaxf(gv.x, gv.y), fmaxf(gv.z, gv.w));
#pragma unroll
    for (int o = 16; o > 0; o >>= 1) {
        mn = fminf(mn, __shfl_xor_sync(0xffffffffu, mn, o));
        mx = fmaxf(mx, __shfl_xor_sync(0xffffffffu, mx, o));
    }
    __shared__ float smn[8], smx[8], ssg[8], ssx[8];
    const int w = tid >> 5, lane = tid & 31;
    if (lane == 0) { smn[w] = mn; smx[w] = mx; }
    __syncthreads();
    mn = smn[0]; mx = smx[0];
#pragma unroll
    for (int i = 1; i < 8; i++) { mn = fminf(mn, smn[i]); mx = fmaxf(mx, smx[i]); }

    const float inv = 1.0f / (mx - mn);
    float4 ng;
    ng.x = (gv.x - mn) * inv; ng.y = (gv.y - mn) * inv;
    ng.z = (gv.z - mn) * inv; ng.w = (gv.w - mn) * inv;

    float sg = ng.x * ng.x + ng.y * ng.y + ng.z * ng.z + ng.w * ng.w;
    float sx = xv.x * xv.x + xv.y * xv.y + xv.z * xv.z + xv.w * xv.w;
#pragma unroll
    for (int o = 16; o > 0; o >>= 1) {
        sg += __shfl_xor_sync(0xffffffffu, sg, o);
        sx += __shfl_xor_sync(0xffffffffu, sx, o);
    }
    if (lane == 0) { ssg[w] = sg; ssx[w] = sx; }
    __syncthreads();
    sg = 0.f; sx = 0.f;
#pragma unroll
    for (int i = 0; i < 8; i++) { sg += ssg[i]; sx += ssx[i]; }

    const float rg = 1.0f / sqrtf(sg);
    const float rx = 1.0f / sqrtf(sx);

    float4 f0, f1;
    f0.x = ng.x * rg; f0.y = xv.x * rx; f0.z = ng.y * rg; f0.w = xv.y * rx;
    f1.x = ng.z * rg; f1.y = xv.z * rx; f1.z = ng.w * rg; f1.w = xv.w * rx;
    float4* pk = reinterpret_cast<float4*>(g_pk + (size_t)row * ND);
    pk[2 * tid + 0] = f0;
    pk[2 * tid + 1] = f1;

    if (tid == 0) {
        const float* o = outputs + row * NC;
        int best = 0; float bv = o[0];
#pragma unroll
        for (int c = 1; c < NC; c++) { float v = o[c]; if (v > bv) { bv = v; best = c; } }
        g_cls[row] = best;
        atomicAdd(&g_counts[best], 1);
    }
}

// ---------------- kernel 2: stable counting sort + tile queue ----------------
__global__ void __launch_bounds__(1024) k_scatter() {
    __shared__ int sbase[NC];
    __shared__ int wcnt[32][NC];
    __shared__ int woff[32][NC];
    __shared__ int tot[NC];
    const int t = threadIdx.x;
    const int lane = t & 31, w = t >> 5;

    if (t == 0) {
        int acc = 0;
        for (int c = 0; c < NC; c++) { g_offsets[c] = acc; sbase[c] = acc; acc += g_counts[c]; }
        int nt = 0;
        for (int c = 0; c < NC; c++) {
            const int tl = (g_counts[c] + TILE - 1) / TILE;
            for (int ti = 0; ti < tl; ti++)
                for (int tj = ti; tj < tl; tj++)
                    g_tiles[nt++] = c | (ti << 4) | (tj << 10);
        }
        g_ntiles = nt;
    }
    __syncthreads();

    for (int chunk = 0; chunk < NB; chunk += 1024) {
        const int r = chunk + t;
        const int myc = g_cls[r];
        int rank = 0;
#pragma unroll
        for (int c = 0; c < NC; c++) {
            const unsigned m = __ballot_sync(0xffffffffu, myc == c);
            if (lane == 0) wcnt[w][c] = __popc(m);
            if (myc == c) rank = __popc(m & ((1u << lane) - 1u));
        }
        __syncthreads();
        if (w < NC) {   // warp w scans class w across the 32 warps
            const int v = wcnt[lane][w];
            int x = v;
#pragma unroll
            for (int o = 1; o < 32; o <<= 1) {
                const int y = __shfl_up_sync(0xffffffffu, x, o);
                if (lane >= o) x += y;
            }
            woff[lane][w] = x - v;
            if (lane == 31) tot[w] = x;
        }
        __syncthreads();
        g_order[sbase[myc] + woff[w][myc] + rank] = r;
        __syncthreads();
        if (w == 0 && lane < NC) sbase[lane] += tot[lane];
        __syncthreads();
    }
}

// ---------------- kernel 3: fused double-Gram + ratio sum ----------------
// 128-thread blocks = warps 0-3 -> all 4 SMSPs (wid%4 mapping). Each block
// processes TWO 64x64 tiles: threads 0-63 -> tile 2*bid, threads 64-127 ->
// tile 2*bid+1, each half with its own double-buffered smem region. Both
// halves run an identical 64-chunk loop so shared barriers align; an
// out-of-range half computes a clamped dummy tile and skips its write.
// Per thread: 8x8 micro-tile, packed f32x2 FMA (lo=g-gram, hi=x-gram),
// LDS:FFMA2 = 1:8, two-sweep ordering (no back-to-back RAW).
__global__ void __launch_bounds__(128, 2) k_gram() {
    extern __shared__ char smem[];

    const int th   = threadIdx.x;
    const int half = th >> 6;            // 0 or 1: which tile
    const int t    = th & 63;
    const int tx   = t & 7;
    const int ty   = t >> 3;

    char* hbase = smem + half * HBYTES;                 // A: [0,16KB), B: [16KB,32KB)
    float* red  = reinterpret_cast<float*>(smem + 2 * HBYTES);

    const int nt   = g_ntiles;
    const int idx  = blockIdx.x * 2 + half;
    const bool valid = idx < nt;
    const int desc = g_tiles[valid ? idx : 0];
    const int c  = desc & 15;
    const int ti = (desc >> 4) & 63;
    const int tj = (desc >> 10) & 63;
    const int nc   = g_counts[c];
    const int base = g_offsets[c];

    // staging: thread t owns row t of A and row t of B (clamped rows masked later)
    const int aPos = ti * TILE + t;
    const int bPos = tj * TILE + t;
    const int aIdx = (aPos < nc) ? g_order[base + aPos] : g_order[base];
    const int bIdx = (bPos < nc) ? g_order[base + bPos] : g_order[base];
    const char* aSrc = (const char*)(g_pk + (size_t)aIdx * ND);  // 8 KB per row
    const char* bSrc = (const char*)(g_pk + (size_t)bIdx * ND);

    const unsigned aDst0 = su32(hbase) + t * 128;           // A buffer 0
    const unsigned bDst0 = su32(hbase + 16384) + t * 128;   // B buffer 0
    const int sw = t & 7;   // row swizzle key

    // stage chunk 0 into buffer 0
#pragma unroll
    for (int s = 0; s < 8; s++) {
        CP_ASYNC16(aDst0 + ((s ^ sw) << 4), aSrc + s * 16);
        CP_ASYNC16(bDst0 + ((s ^ sw) << 4), bSrc + s * 16);
    }
    CP_COMMIT();

    unsigned long long acc[64];
#pragma unroll
    for (int i = 0; i < 64; i++) acc[i] = 0ull;

    for (int ch = 0; ch < NCHUNK; ch++) {
        const int cur = ch & 1;

        if (ch + 1 < NCHUNK) {   // stage next chunk into the other buffer
            const unsigned aDstN = aDst0 + (cur ^ 1) * 8192;
            const unsigned bDstN = bDst0 + (cur ^ 1) * 8192;
            const char* aS = aSrc + (ch + 1) * 128;
            const char* bS = bSrc + (ch + 1) * 128;
#pragma unroll
            for (int s = 0; s < 8; s++) {
                CP_ASYNC16(aDstN + ((s ^ sw) << 4), aS + s * 16);
                CP_ASYNC16(bDstN + ((s ^ sw) << 4), bS + s * 16);
            }
            CP_COMMIT();
            CP_WAIT(1);          // current chunk's group complete; next stays in flight
        } else {
            CP_WAIT(0);
        }
        __syncthreads();         // both halves aligned; copies visible

        const char* Ab = hbase + cur * 8192;
        const char* Bb = hbase + 16384 + cur * 8192;
#pragma unroll
        for (int cc = 0; cc < 8; cc++) {     // 2 k per slot
            ulonglong2 af[8], bf[8];
#pragma unroll
            for (int i = 0; i < 8; i++) {
                const int r = ty + 8 * i;    // r&7 distinct across i -> swizzle-clean
                af[i] = *reinterpret_cast<const ulonglong2*>(
                            Ab + r * 128 + ((cc ^ (r & 7)) << 4));
            }
#pragma unroll
            for (int j = 0; j < 8; j++) {
                const int r = tx + 8 * j;
                bf[j] = *reinterpret_cast<const ulonglong2*>(
                            Bb + r * 128 + ((cc ^ (r & 7)) << 4));
            }
            // two-sweep: x-parts for all j, then y-parts — no back-to-back RAW
#pragma unroll
            for (int i = 0; i < 8; i++) {
#pragma unroll
                for (int j = 0; j < 8; j++) ffma2(acc[i * 8 + j], af[i].x, bf[j].x);
#pragma unroll
                for (int j = 0; j < 8; j++) ffma2(acc[i * 8 + j], af[i].y, bf[j].y);
            }
        }
        __syncthreads();         // compute done before buffer reuse
    }

    // masked ratio: pair valid iff both rows exist and rp < cp (strict upper)
    float sum = 0.f;
#pragma unroll
    for (int i = 0; i < 8; i++) {
        const int rp = ti * TILE + ty + 8 * i;
#pragma unroll
        for (int j = 0; j < 8; j++) {
            const int cp = tj * TILE + tx + 8 * j;
            if (rp < nc && cp < nc && rp < cp) {
                const unsigned long long a = acc[i * 8 + j];
                const float cg = __uint_as_float((unsigned)(a & 0xffffffffu));
                const float cx = __uint_as_float((unsigned)(a >> 32));
                sum += (1.0f - cg) / (1.0f - cx);
            }
        }
    }

    // per-half deterministic reduction
    red[th] = sum;
    __syncthreads();
#pragma unroll
    for (int s = 32; s > 0; s >>= 1) {
        if (t < s) red[half * 64 + t] += red[half * 64 + t + s];
        __syncthreads();
    }
    if (t == 0 && valid) g_partials[idx] = red[half * 64];
}

// ---------------- kernel 4: final deterministic reduction ----------------
__global__ void __launch_bounds__(256) k_final(float* __restrict__ out) {
    __shared__ float red[256];
    const int t = threadIdx.x;
    const int n = g_ntiles;
    float s = 0.f;
    for (int i = t; i < n; i += 256) s += g_partials[i];
    red[t] = s;
    __syncthreads();
#pragma unroll
    for (int st = 128; st > 0; st >>= 1) {
        if (t < st) red[t] += red[t + st];
        __syncthreads();
    }
    if (t == 0) out[0] = red[0] / (float)NB;
}

// ---------------- launch ----------------
extern "C" void kernel_launch(void* const* d_in, const int* in_sizes, int n_in,
                              void* d_out, int out_size) {
    (void)in_sizes; (void)n_in; (void)out_size;
    const float* outputs = (const float*)d_in[0];
    const float* grad    = (const float*)d_in[1];
    const float* xin     = (const float*)d_in[2];
    float* out = (float*)d_out;

    // idempotent, capture-safe (not a stream op, no allocation)
    cudaFuncSetAttribute(k_gram, cudaFuncAttributeMaxDynamicSharedMemorySize, SMEMSZ);

    k_zero<<<1, 32>>>();
    k_prep<<<NB, 256>>>(outputs, grad, xin);
    k_scatter<<<1, 1024>>>();
    k_gram<<<(MAXT + 1) / 2, 128, SMEMSZ>>>();
    k_final<<<1, 256>>>(out);
}